// round 9
// baseline (speedup 1.0000x reference)
#include <cuda_runtime.h>
#include <float.h>

#define L_SEQ 4096
#define N_TOTAL 512
#define WPB 8            // warps per block
#define TPB (WPB * 32)   // 256 threads
#define PAD_MAX 4096     // P <= 4094
#define LP_MAX (L_SEQ + 2 * PAD_MAX)   // 12288 floats
// dynamic smem layout: [0, LP_MAX) = padded x ; then WPB floats mx ; WPB ints cnt ; 1 int item
#define SMEM_WORDS (LP_MAX + WPB + WPB + 1)
#define SMEM_BYTES (SMEM_WORDS * 4)
#define MAX_B 64

__device__ int g_inv[N_TOTAL];
__device__ int g_P;
__device__ int g_ctr[MAX_B];

// Reset work counters, build inverse permutation, recover P.
__global__ void setup_kernel(const int* __restrict__ perm,
                             const int* __restrict__ off0,
                             const int* __restrict__ lout0,
                             int n_perm) {
    int j = threadIdx.x;
    if (j < MAX_B) g_ctr[j] = 0;
    if (j < n_perm) g_inv[perm[j]] = j;
    if (j == 0) {
        int d6  = off0[6] - off0[0];
        int pad = (lout0[0] - L_SEQ + d6) / 2;
        g_P = off0[0] + pad;
    }
}

// Sliding-window 1D conv along m for one thread: s_m = bsv + sum_k wk[k]*p[(m+k)*d],
// m in [0, steps). Window rotation fully unrolled (R5 form — proven fastest core).
template<int KS>
__device__ __forceinline__ void conv_lane(
    const float* __restrict__ p, int steps, int d, float bsv,
    const float* __restrict__ wk, float& mx, int& cnt)
{
    if (steps <= 0) return;
    if (steps >= KS) {
        float y[KS];
#pragma unroll
        for (int j = 0; j < KS - 1; j++) y[j] = p[j * d];
        const float* pl = p + (KS - 1) * d;
        int i = 0;
        for (; i + KS <= steps; i += KS) {
#pragma unroll
            for (int u = 0; u < KS; u++) {
                y[(u + KS - 1) % KS] = *pl; pl += d;
                float s = bsv;
#pragma unroll
                for (int k = 0; k < KS; k++)
                    s = fmaf(wk[k], y[(u + k) % KS], s);
                mx = fmaxf(mx, s);
                cnt += (s > 0.0f);
            }
        }
        for (; i < steps; i++) {
            const float* q = p + i * d;
            float s = bsv;
#pragma unroll
            for (int k = 0; k < KS; k++) s = fmaf(wk[k], q[k * d], s);
            mx = fmaxf(mx, s);
            cnt += (s > 0.0f);
        }
    } else {
        for (int i = 0; i < steps; i++) {
            const float* q = p + i * d;
            float s = bsv;
#pragma unroll
            for (int k = 0; k < KS; k++) s = fmaf(wk[k], q[k * d], s);
            mx = fmaxf(mx, s);
            cnt += (s > 0.0f);
        }
    }
}

// Block-cooperative item: all 256 threads share one (kernel gi) work item.
template<int KS>
__device__ __forceinline__ void run_group(
    const float* __restrict__ sx,          // zero-padded: x lives at [P, P+L)
    const float* __restrict__ w, const float* __restrict__ bias,
    const int*  __restrict__ off, const int* __restrict__ lout,
    float* __restrict__ out, int gi, int base, int b, int stride,
    float* __restrict__ red_mx, int* __restrict__ red_cnt)
{
    const int tid  = threadIdx.x;
    const int lane = tid & 31;
    const int wrp  = tid >> 5;

    float wk[KS];
#pragma unroll
    for (int k = 0; k < KS; k++) wk[k] = __ldg(&w[gi * KS + k]);
    const int   o0  = __ldg(&off[gi * KS]);           // padded-array base for tap 0
    const int   d   = __ldg(&off[gi * KS + 1]) - o0;  // dilation
    const float bsv = __ldg(&bias[gi]);
    const int   lo  = __ldg(&lout[gi]);

    float mx  = -FLT_MAX;
    int   cnt = 0;
    const float* px = sx + o0;

    if (d < TPB) {
        // thread -> (residue r, chunk g); uniform odd chunk size => conflict-free
        // within each warp (addresses of same-r lanes differ by mc*d, mc odd).
        const int r = tid % d;
        const int g = tid / d;
        const int Mmax = (lo + d - 1) / d;
        const int Gmin = TPB / d;                  // groups available per residue
        int mc = (Mmax + Gmin - 1) / Gmin;
        mc |= 1;                                   // round up to odd
        const int Mr = (r < lo) ? (lo - r + d - 1) / d : 0;
        int m0 = g * mc;
        int m1 = m0 + mc; if (m1 > Mr) m1 = Mr;
        if (m0 < m1)
            conv_lane<KS>(px + r + d * m0, m1 - m0, d, bsv, wk, mx, cnt);
    } else {
        // threads = consecutive residues (consecutive addresses: conflict-free)
        for (int rb = 0; rb < d; rb += TPB) {
            const int r = rb + tid;
            if (r < d) {
                const int Mr = (r < lo) ? (lo - r + d - 1) / d : 0;
                conv_lane<KS>(px + r, Mr, d, bsv, wk, mx, cnt);
            }
        }
    }

    // warp reductions
#pragma unroll
    for (int o = 16; o; o >>= 1) {
        mx   = fmaxf(mx, __shfl_xor_sync(0xffffffffu, mx, o));
        cnt += __shfl_xor_sync(0xffffffffu, cnt, o);
    }
    if (lane == 0) { red_mx[wrp] = mx; red_cnt[wrp] = cnt; }
    __syncthreads();

    if (tid == 0) {
        float m = red_mx[0];
        int   c = red_cnt[0];
#pragma unroll
        for (int i = 1; i < WPB; i++) {
            m = fmaxf(m, red_mx[i]);
            c += red_cnt[i];
        }
        int col = g_inv[base + gi];
        out[b * stride + 2 * col]     = m;
        out[b * stride + 2 * col + 1] = (float)c / (float)lo;
    }
}

__global__ __launch_bounds__(TPB)
void rocket_all_kernel(
    const float* __restrict__ x,
    const float* __restrict__ w0, const float* __restrict__ b0,
    const int*  __restrict__ off0, const int* __restrict__ lout0, int n0,
    const float* __restrict__ w1, const float* __restrict__ b1,
    const int*  __restrict__ off1, const int* __restrict__ lout1, int n1,
    const float* __restrict__ w2, const float* __restrict__ b2,
    const int*  __restrict__ off2, const int* __restrict__ lout2, int n2,
    float* __restrict__ out, int stride)
{
    extern __shared__ float smem[];
    float* sx      = smem;                       // LP_MAX floats
    float* red_mx  = smem + LP_MAX;              // WPB floats
    int*   red_cnt = (int*)(smem + LP_MAX + WPB);// WPB ints
    int*   s_item  = (int*)(smem + LP_MAX + 2 * WPB);

    const int b = blockIdx.y;
    const int P = g_P;
    const int N = n0 + n1 + n2;
    const int tid = threadIdx.x;

    // zero pad regions [0,P) and [P+L, P+L+P)
    for (int i = tid; i < P; i += TPB) {
        sx[i]             = 0.0f;
        sx[P + L_SEQ + i] = 0.0f;
    }
    // stage x[b] into sx[P .. P+L): P even => float2-aligned
    {
        const float2* xb2 = (const float2*)(x + (size_t)b * L_SEQ);
        float2* dst = (float2*)(sx + P);
        for (int i = tid; i < L_SEQ / 2; i += TPB)
            dst[i] = xb2[i];
    }

    // block-level work stealing: whole block cooperates on one item at a time
    for (;;) {
        __syncthreads();                       // protects s_item / red arrays reuse
        if (tid == 0) *s_item = atomicAdd(&g_ctr[b], 1);
        __syncthreads();
        const int item = *s_item;
        if (item >= N) break;

        if (item < n0) {
            run_group<7>(sx, w0, b0, off0, lout0, out, item, 0, b, stride, red_mx, red_cnt);
        } else if (item < n0 + n1) {
            run_group<9>(sx, w1, b1, off1, lout1, out, item - n0, n0, b, stride, red_mx, red_cnt);
        } else {
            run_group<11>(sx, w2, b2, off2, lout2, out, item - n0 - n1, n0 + n1, b, stride, red_mx, red_cnt);
        }
    }
}

extern "C" void kernel_launch(void* const* d_in, const int* in_sizes, int n_in,
                              void* d_out, int out_size) {
    // Dict order:      x, perm, P, w0,b0,off0,lout0, w1,b1,off1,lout1, w2,b2,off2,lout2
    // Signature order: x, w0,b0,off0,lout0, w1,b1,off1,lout1, w2,b2,off2,lout2, perm, P
    int ix, iperm, ig0, ig1, ig2;
    if (n_in >= 3 && in_sizes[1] == N_TOTAL && in_sizes[2] == 1) {
        ix = 0; iperm = 1; ig0 = 3; ig1 = 7; ig2 = 11;
    } else {
        ix = 0; ig0 = 1; ig1 = 5; ig2 = 9; iperm = 13;
    }

    const float* x     = (const float*)d_in[ix];
    const int*   perm  = (const int*)  d_in[iperm];

    const float* w0    = (const float*)d_in[ig0 + 0];
    const float* b0    = (const float*)d_in[ig0 + 1];
    const int*   off0  = (const int*)  d_in[ig0 + 2];
    const int*   lout0 = (const int*)  d_in[ig0 + 3];
    const float* w1    = (const float*)d_in[ig1 + 0];
    const float* b1    = (const float*)d_in[ig1 + 1];
    const int*   off1  = (const int*)  d_in[ig1 + 2];
    const int*   lout1 = (const int*)  d_in[ig1 + 3];
    const float* w2    = (const float*)d_in[ig2 + 0];
    const float* b2    = (const float*)d_in[ig2 + 1];
    const int*   off2  = (const int*)  d_in[ig2 + 2];
    const int*   lout2 = (const int*)  d_in[ig2 + 3];

    const int n0 = in_sizes[ig0 + 1];
    const int n1 = in_sizes[ig1 + 1];
    const int n2 = in_sizes[ig2 + 1];
    const int B  = in_sizes[ix] / L_SEQ;
    const int N  = n0 + n1 + n2;
    const int stride = 2 * N;

    static bool attr_set = false;
    if (!attr_set) {
        cudaFuncSetAttribute(rocket_all_kernel,
                             cudaFuncAttributeMaxDynamicSharedMemorySize, SMEM_BYTES);
        attr_set = true;
    }

    setup_kernel<<<1, N_TOTAL>>>(perm, off0, lout0, in_sizes[iperm]);

    // persistent balanced grid: ~4 blocks/SM * 148 SMs
    int bpb = 592 / (B > 0 ? B : 1);
    if (bpb < 1) bpb = 1;
    if (bpb > N) bpb = N;      // at most one block per item

    dim3 grid(bpb, B);
    rocket_all_kernel<<<grid, TPB, SMEM_BYTES>>>(
        x,
        w0, b0, off0, lout0, n0,
        w1, b1, off1, lout1, n1,
        w2, b2, off2, lout2, n2,
        (float*)d_out, stride);
}